// round 14
// baseline (speedup 1.0000x reference)
#include <cuda_runtime.h>
#include <cuda_bf16.h>
#include <mma.h>
#include <stdint.h>
#include <math.h>

using namespace nvcuda;

typedef unsigned long long u64;
typedef unsigned int u32;

// ---------------------------------------------------------------------------
// Scratch (static __device__ arrays; no dynamic allocation allowed)
// ---------------------------------------------------------------------------
#define MAX_N 50048

__device__ __align__(16) float g_segsum[MAX_N];
__device__ __align__(16) float g_cnt[MAX_N];
__device__ __align__(16) float g_agg[50000 * 64];

// Per-node precomputed GEMM slabs (fp32):
//   g_P[n][0..255]   = nf[n] @ W1cat[64:128]   (src-role contribution)
//   g_P[n][256..511] = nf[n] @ W1cat[128:192]  (dst-role contribution)
__device__ __align__(16) float g_P[(size_t)MAX_N * 512];

// Pre-split weights (filled by k_prep), row-major bf16 hi/lo images.
// W1cat: [192][256]  (cols 0..127 = We1, 128..255 = Wa1)
__device__ __align__(16) __nv_bfloat16 gW1h[192 * 256];
__device__ __align__(16) __nv_bfloat16 gW1l[192 * 256];
// We2: [128][64]
__device__ __align__(16) __nv_bfloat16 gW2h[128 * 64];
__device__ __align__(16) __nv_bfloat16 gW2l[128 * 64];

// fp32 -> bf16 hi/lo split
__device__ __forceinline__ void split2(float v, unsigned short& h, unsigned short& l) {
    __nv_bfloat16 bh = __float2bfloat16_rn(v);
    float r = v - __bfloat162float(bh);
    __nv_bfloat16 bl = __float2bfloat16_rn(r);
    h = __bfloat16_as_ushort(bh);
    l = __bfloat16_as_ushort(bl);
}

__device__ __forceinline__ void red_add_v4(float* p, float4 v) {
    asm volatile("red.global.add.v4.f32 [%0], {%1,%2,%3,%4};"
                 :: "l"(__cvta_generic_to_global(p)),
                    "f"(v.x), "f"(v.y), "f"(v.z), "f"(v.w)
                 : "memory");
}

// ---------------------------------------------------------------------------
// K0: zero-init scratch
// ---------------------------------------------------------------------------
__global__ void k0_init(int N) {
    int i = blockIdx.x * blockDim.x + threadIdx.x;
    if (i < N) {
        g_segsum[i] = 0.0f;
        g_cnt[i]    = 0.0f;
    }
    if (i < N * 64) g_agg[i] = 0.0f;
}

// ---------------------------------------------------------------------------
// K_PREP: bf16 hi/lo split of weights into row-major global images.
// ---------------------------------------------------------------------------
__global__ void k_prep(const float* __restrict__ We1, const float* __restrict__ Wa1,
                       const float* __restrict__ We2) {
    int idx = blockIdx.x * blockDim.x + threadIdx.x;
    if (idx < 49152) {                    // 192*256
        int n = idx & 255, k = idx >> 8;
        float v = (n < 128) ? We1[(size_t)k * 128 + n]
                            : Wa1[(size_t)k * 128 + (n - 128)];
        unsigned short h, l; split2(v, h, l);
        gW1h[idx] = __ushort_as_bfloat16(h);
        gW1l[idx] = __ushort_as_bfloat16(l);
    } else if (idx < 49152 + 8192) {      // 128*64
        int t = idx - 49152;
        float v = We2[t];
        unsigned short h, l; split2(v, h, l);
        gW2h[t] = __ushort_as_bfloat16(h);
        gW2l[t] = __ushort_as_bfloat16(l);
    }
}

// ---------------------------------------------------------------------------
// Shared WMMA types / layout constants
// ---------------------------------------------------------------------------
typedef wmma::fragment<wmma::accumulator, 16, 16, 16, float> FragC;
typedef wmma::fragment<wmma::matrix_a, 16, 16, 16, __nv_bfloat16, wmma::row_major> FragA;
typedef wmma::fragment<wmma::matrix_b, 16, 16, 16, __nv_bfloat16, wmma::row_major> FragB;

#define LDX  72
#define LDW1 264
#define LDC  136
#define LDH  136
#define LDW2 72

// k1 smem byte map (total 212480)
#define SM_XH   0
#define SM_XL   18432
#define SM_W1H  36864
#define SM_W1L  70656
#define SM_C    104448
#define SM_W2H  174080
#define SM_W2L  192512
#define SM_HH   0
#define SM_HL   34816
#define SM_SRC  210944
#define SM_DST  211456
#define SM_LOG  211968
#define K1_SMEM_BYTES 212480
// kp uses [0, 104448) of the same map
#define KP_SMEM_BYTES 104448

// gather 128 rows x 64 cols fp32 -> split -> sXh/sXl  (rows guarded)
__device__ __forceinline__ void gather_split_64(
    char* smc, const float* __restrict__ base, int row0, int rowMax, int tid)
{
    __nv_bfloat16* sXh = (__nv_bfloat16*)(smc + SM_XH);
    __nv_bfloat16* sXl = (__nv_bfloat16*)(smc + SM_XL);
    for (int it = 0; it < 4; ++it) {
        int task = it * 512 + tid;        // 0..2047 = 128 rows x 16 float4
        int m = task >> 4;
        int s = task & 15;
        float4 v = make_float4(0.f, 0.f, 0.f, 0.f);
        if (row0 + m < rowMax)
            v = *(const float4*)&base[(size_t)(row0 + m) * 64 + s * 4];
        unsigned short h0,l0,h1,l1,h2,l2,h3,l3;
        split2(v.x, h0, l0); split2(v.y, h1, l1);
        split2(v.z, h2, l2); split2(v.w, h3, l3);
        u32* ph = (u32*)(sXh + (size_t)m * LDX + s * 4);
        u32* pl = (u32*)(sXl + (size_t)m * LDX + s * 4);
        ph[0] = (u32)h0 | ((u32)h1 << 16);
        ph[1] = (u32)h2 | ((u32)h3 << 16);
        pl[0] = (u32)l0 | ((u32)l1 << 16);
        pl[1] = (u32)l2 | ((u32)l3 << 16);
    }
}

// stage 64 rows (rowbase..) x 256 cols of W1cat h+l into sW1
__device__ __forceinline__ void stage_w1_slab(char* smc, int rowbase, int tid) {
    const u32* sh = (const u32*)gW1h;
    const u32* sl = (const u32*)gW1l;
    u32* dh = (u32*)(smc + SM_W1H);
    u32* dl = (u32*)(smc + SM_W1L);
    for (int i = tid; i < 16384; i += 512) {     // 2 imgs x 64 rows x 128 u32
        int img = i >> 13;
        int rem = i & 8191;
        int row = rem >> 7, c2 = rem & 127;
        u32 v = (img ? sl : sh)[(size_t)(rowbase + row) * 128 + c2];
        (img ? dl : dh)[row * (LDW1 / 2) + c2] = v;
    }
}

// ---------------------------------------------------------------------------
// KP: per-node P table.  CTA = 128 nodes, 512 threads, 2 phases (src/dst role).
// ---------------------------------------------------------------------------
__global__ __launch_bounds__(512, 1)
void kp_nodes(const float* __restrict__ nf, int N)
{
    extern __shared__ char smc[];
    const int tid = threadIdx.x;
    const int w   = tid >> 5;
    const int wr  = w >> 1;
    const int wc  = w & 1;
    const int n0  = blockIdx.x * 128;

    gather_split_64(smc, nf, n0, N, tid);

    __nv_bfloat16* sXh  = (__nv_bfloat16*)(smc + SM_XH);
    __nv_bfloat16* sXl  = (__nv_bfloat16*)(smc + SM_XL);
    __nv_bfloat16* sW1h = (__nv_bfloat16*)(smc + SM_W1H);
    __nv_bfloat16* sW1l = (__nv_bfloat16*)(smc + SM_W1L);

    #pragma unroll 1
    for (int ph = 0; ph < 2; ++ph) {
        __syncthreads();
        stage_w1_slab(smc, 64 + ph * 64, tid);
        __syncthreads();

        FragC cc[8];
        #pragma unroll
        for (int j = 0; j < 8; ++j) wmma::fill_fragment(cc[j], 0.0f);
        #pragma unroll 1
        for (int k = 0; k < 4; ++k) {
            FragA ah, al;
            wmma::load_matrix_sync(ah, sXh + (size_t)wr * 16 * LDX + k * 16, LDX);
            wmma::load_matrix_sync(al, sXl + (size_t)wr * 16 * LDX + k * 16, LDX);
            #pragma unroll
            for (int j = 0; j < 8; ++j) {
                int col = wc * 128 + j * 16;
                FragB bh, bl;
                wmma::load_matrix_sync(bh, sW1h + (size_t)k * 16 * LDW1 + col, LDW1);
                wmma::load_matrix_sync(bl, sW1l + (size_t)k * 16 * LDW1 + col, LDW1);
                wmma::mma_sync(cc[j], ah, bh, cc[j]);
                wmma::mma_sync(cc[j], ah, bl, cc[j]);
                wmma::mma_sync(cc[j], al, bh, cc[j]);
            }
        }
        // store straight to global (g_P padded to MAX_N rows; always in-bounds)
        float* prow = g_P + (size_t)(n0 + wr * 16) * 512 + ph * 256 + wc * 128;
        #pragma unroll
        for (int j = 0; j < 8; ++j)
            wmma::store_matrix_sync(prow + j * 16, cc[j], 512, wmma::mem_row_major);
    }
}

// ---------------------------------------------------------------------------
// K1: edge kernel.  GEMM1 over ef slab only (K=64); P_src/P_dst added as
//     exact fp32 in COALESCED passes (warp = 32 consecutive cols of one row).
//     Sequential He-GEMM -> Ha-GEMM to halve live fragments (reg relief).
// ---------------------------------------------------------------------------
__global__ __launch_bounds__(512, 1)
void k1_edge(const float* __restrict__ ef,
             const float* __restrict__ be1, const float* __restrict__ be2,
             const float* __restrict__ ba1, const float* __restrict__ ba2,
             const float* __restrict__ Wa2,
             const int* __restrict__ src,   const int* __restrict__ dst,
             float* __restrict__ uef_out, int E)
{
    extern __shared__ char smc[];
    const int tid = threadIdx.x;
    const int w   = tid >> 5;
    const int wr  = w >> 1;          // row tile 0..7
    const int wc  = w & 1;           // col half 0..1
    const int e0  = blockIdx.x * 128;

    float* sLog = (float*)(smc + SM_LOG);
    int*   sSrc = (int*)(smc + SM_SRC);
    int*   sDst = (int*)(smc + SM_DST);
    if (tid < 128) {
        sLog[tid] = 0.0f;
        int e = e0 + tid;
        sSrc[tid] = (e < E) ? src[e] : 0;
        sDst[tid] = (e < E) ? dst[e] : 0;
    }

    gather_split_64(smc, ef, e0, E, tid);     // contiguous, fully coalesced
    stage_w1_slab(smc, 0, tid);               // W1cat rows 0..63, all 256 cols
    __syncthreads();                          // --- sync A ---

    __nv_bfloat16* sXh  = (__nv_bfloat16*)(smc + SM_XH);
    __nv_bfloat16* sXl  = (__nv_bfloat16*)(smc + SM_XL);
    __nv_bfloat16* sW1h = (__nv_bfloat16*)(smc + SM_W1H);
    __nv_bfloat16* sW1l = (__nv_bfloat16*)(smc + SM_W1L);
    float* sC = (float*)(smc + SM_C);

    // --- GEMM1a (He cols wc*64..): only 4 C frags live ---
    {
        FragC cHe[4];
        #pragma unroll
        for (int j = 0; j < 4; ++j) wmma::fill_fragment(cHe[j], 0.0f);
        #pragma unroll 1
        for (int k = 0; k < 4; ++k) {
            FragA ah, al;
            wmma::load_matrix_sync(ah, sXh + (size_t)wr * 16 * LDX + k * 16, LDX);
            wmma::load_matrix_sync(al, sXl + (size_t)wr * 16 * LDX + k * 16, LDX);
            #pragma unroll
            for (int j = 0; j < 4; ++j) {
                int ce = wc * 64 + j * 16;
                FragB bh, bl;
                wmma::load_matrix_sync(bh, sW1h + (size_t)k * 16 * LDW1 + ce, LDW1);
                wmma::load_matrix_sync(bl, sW1l + (size_t)k * 16 * LDW1 + ce, LDW1);
                wmma::mma_sync(cHe[j], ah, bh, cHe[j]);
                wmma::mma_sync(cHe[j], ah, bl, cHe[j]);
                wmma::mma_sync(cHe[j], al, bh, cHe[j]);
            }
        }
        #pragma unroll
        for (int j = 0; j < 4; ++j)
            wmma::store_matrix_sync(sC + (size_t)wr * 16 * LDC + wc * 64 + j * 16,
                                    cHe[j], LDC, wmma::mem_row_major);
    }

    // --- GEMM1b (Ha cols 128+wc*64..): frags held briefly ---
    FragC cHa[4];
    #pragma unroll
    for (int j = 0; j < 4; ++j) wmma::fill_fragment(cHa[j], 0.0f);
    #pragma unroll 1
    for (int k = 0; k < 4; ++k) {
        FragA ah, al;
        wmma::load_matrix_sync(ah, sXh + (size_t)wr * 16 * LDX + k * 16, LDX);
        wmma::load_matrix_sync(al, sXl + (size_t)wr * 16 * LDX + k * 16, LDX);
        #pragma unroll
        for (int j = 0; j < 4; ++j) {
            int ca = 128 + wc * 64 + j * 16;
            FragB bh, bl;
            wmma::load_matrix_sync(bh, sW1h + (size_t)k * 16 * LDW1 + ca, LDW1);
            wmma::load_matrix_sync(bl, sW1l + (size_t)k * 16 * LDW1 + ca, LDW1);
            wmma::mma_sync(cHa[j], ah, bh, cHa[j]);
            wmma::mma_sync(cHa[j], ah, bl, cHa[j]);
            wmma::mma_sync(cHa[j], al, bh, cHa[j]);
        }
    }
    __syncthreads();                          // --- sync B: He in sC; X dead ---

    // --- He pass: sC + P -> bias/ReLU/split -> sH (overlays sX; COALESCED) ---
    __nv_bfloat16* sHh = (__nv_bfloat16*)(smc + SM_HH);
    __nv_bfloat16* sHl = (__nv_bfloat16*)(smc + SM_HL);
    #pragma unroll 1
    for (int it = 0; it < 32; ++it) {
        int i = it * 512 + tid;
        int row = i >> 7, col = i & 127;
        const float* ps = g_P + (size_t)sSrc[row] * 512;         // He src part
        const float* pd = g_P + (size_t)sDst[row] * 512 + 256;   // He dst part
        float v = fmaxf(sC[row * LDC + col] + ps[col] + pd[col] + be1[col], 0.0f);
        unsigned short h, l; split2(v, h, l);
        sHh[(size_t)row * LDH + col] = __ushort_as_bfloat16(h);
        sHl[(size_t)row * LDH + col] = __ushort_as_bfloat16(l);
    }
    __syncthreads();                          // --- sync C: sC free ---

    // --- dump Ha -> sC ---
    #pragma unroll
    for (int j = 0; j < 4; ++j)
        wmma::store_matrix_sync(sC + (size_t)wr * 16 * LDC + wc * 64 + j * 16,
                                cHa[j], LDC, wmma::mem_row_major);
    __syncthreads();                          // --- sync D ---

    // --- attn pass (COALESCED: warp = one row x 32 cols; shfl row-reduce) ---
    {
        int lane = tid & 31;
        #pragma unroll 1
        for (int it = 0; it < 32; ++it) {
            int i = it * 512 + tid;
            int row = i >> 7, col = i & 127;
            const float* ps = g_P + (size_t)sSrc[row] * 512 + 128;   // attn src
            const float* pd = g_P + (size_t)sDst[row] * 512 + 384;   // attn dst
            float h = sC[row * LDC + col] + ps[col] + pd[col] + ba1[col];
            float p = fmaxf(h, 0.0f) * Wa2[col];
            p += __shfl_xor_sync(0xFFFFFFFFu, p, 16);
            p += __shfl_xor_sync(0xFFFFFFFFu, p, 8);
            p += __shfl_xor_sync(0xFFFFFFFFu, p, 4);
            p += __shfl_xor_sync(0xFFFFFFFFu, p, 2);
            p += __shfl_xor_sync(0xFFFFFFFFu, p, 1);
            if (lane == 0) atomicAdd(&sLog[row], p);
        }
        // stage We2 (h+l)
        const u32* sh = (const u32*)gW2h;
        const u32* sl = (const u32*)gW2l;
        u32* dh = (u32*)(smc + SM_W2H);
        u32* dl = (u32*)(smc + SM_W2L);
        for (int i = tid; i < 8192; i += 512) {   // 2 imgs x 128 rows x 32 u32
            int img = i >> 12;
            int rem = i & 4095;
            int r2 = rem >> 5, c2 = rem & 31;
            u32 v = (img ? sl : sh)[r2 * 32 + c2];
            (img ? dl : dh)[r2 * (LDW2 / 2) + c2] = v;
        }
    }
    __syncthreads();                          // --- sync E ---

    // --- GEMM2: uef = H @ We2 (K=128; each warp 2 j-tiles of 32 cols) ---
    {
        FragC cU[2];
        wmma::fill_fragment(cU[0], 0.0f);
        wmma::fill_fragment(cU[1], 0.0f);
        __nv_bfloat16* sW2h = (__nv_bfloat16*)(smc + SM_W2H);
        __nv_bfloat16* sW2l = (__nv_bfloat16*)(smc + SM_W2L);
        #pragma unroll 1
        for (int k = 0; k < 8; ++k) {
            FragA ah, al;
            wmma::load_matrix_sync(ah, sHh + (size_t)wr * 16 * LDH + k * 16, LDH);
            wmma::load_matrix_sync(al, sHl + (size_t)wr * 16 * LDH + k * 16, LDH);
            #pragma unroll
            for (int j = 0; j < 2; ++j) {
                int col = wc * 32 + j * 16;
                FragB bh, bl;
                wmma::load_matrix_sync(bh, sW2h + (size_t)k * 16 * LDW2 + col, LDW2);
                wmma::load_matrix_sync(bl, sW2l + (size_t)k * 16 * LDW2 + col, LDW2);
                wmma::mma_sync(cU[j], ah, bh, cU[j]);
                wmma::mma_sync(cU[j], ah, bl, cU[j]);
                wmma::mma_sync(cU[j], al, bh, cU[j]);
            }
        }
        #pragma unroll
        for (int j = 0; j < 2; ++j)
            wmma::store_matrix_sync(sC + (size_t)wr * 16 * LDC + wc * 32 + j * 16,
                                    cU[j], LDC, wmma::mem_row_major);
    }
    __syncthreads();                          // --- sync F ---

    // --- epilogue: logits->exp, segment atomics, uef write, aggregate ---
    if (tid < 128) {
        int e = e0 + tid;
        if (e < E) {
            float lg = sLog[tid] + ba2[0];
            float ex = __expf(lg);        // no max-subtraction: logits are O(1)
            int d = sDst[tid];
            atomicAdd(&g_segsum[d], ex);
            atomicAdd(&g_cnt[d], 1.0f);
            float* orow = uef_out + (size_t)e * 64;
            float* arow = g_agg + (size_t)d * 64;
            const float* crow = sC + (size_t)tid * LDC;
            #pragma unroll
            for (int q = 0; q < 16; ++q) {
                float4 c = *(const float4*)(crow + q * 4);
                float4 o = make_float4(c.x + be2[q*4 + 0], c.y + be2[q*4 + 1],
                                       c.z + be2[q*4 + 2], c.w + be2[q*4 + 3]);
                *(float4*)(orow + q * 4) = o;
                float4 vv = make_float4(o.x * ex, o.y * ex, o.z * ex, o.w * ex);
                red_add_v4(arow + q * 4, vv);
            }
        }
    }
}

// ---------------------------------------------------------------------------
// K3: node MLP (proven version: 256 threads, FFMA2+DUP2)
// ---------------------------------------------------------------------------
#define FMA2(d, a, b) asm("fma.rn.f32x2 %0, %1, %2, %0;" : "+l"(d) : "l"(a), "l"(b))
#define DUP2(d, s)    asm("mov.b64 %0, {%1, %1};" : "=l"(d) : "f"(s))
union F4U2 { float4 f; u64 u[2]; };
union U2F  { u64 u; float2 f; };
__device__ __forceinline__ float lane_of(u64 v, int h) {
    U2F t; t.u = v; return h ? t.f.y : t.f.x;
}

#define NODE_SMEM_FLOATS (16384 + 2048 + 8448 + 8192 + 128)
#define NODE_SMEM_BYTES  (NODE_SMEM_FLOATS * 4)

__global__ __launch_bounds__(256, 1)
void k3_node(const float* __restrict__ nf,
             const float* __restrict__ Wn1, const float* __restrict__ bn1,
             const float* __restrict__ Wn2, const float* __restrict__ bn2,
             float* __restrict__ unf_out, int N)
{
    extern __shared__ float sm[];
    float* sX   = sm;            // [128][128]
    float* sW   = sX + 16384;    // [32][64]
    float* sH   = sW + 2048;     // [64][132]
    float* sWn2 = sH + 8448;     // [128][64]
    float* sRs  = sWn2 + 8192;   // [128]

    const int tid = threadIdx.x;
    const int tx  = tid & 15;
    const int ty  = tid >> 4;
    const int n0  = blockIdx.x * 128;

    #pragma unroll
    for (int i = tid; i < 2048; i += 256)
        ((float4*)sWn2)[i] = ((const float4*)Wn2)[i];
    if (tid < 128) {
        int n = n0 + tid;
        float rs = 0.0f;
        if (n < N) {
            float c = g_cnt[n];
            if (c > 0.5f) rs = 1.0f / (g_segsum[n] * c);
        }
        sRs[tid] = rs;
    }
    __syncthreads();

    for (int it = 0; it < 16; ++it) {
        int task = it * 256 + tid;
        if (task >= 4096) break;
        int m = task & 127;
        int s = task >> 7;
        int n = n0 + m;
        float4 v = make_float4(0.f, 0.f, 0.f, 0.f);
        if (n < N) {
            if (s < 16) {
                v = *(const float4*)&g_agg[(size_t)n * 64 + s * 4];
                float rs = sRs[m];
                v.x *= rs; v.y *= rs; v.z *= rs; v.w *= rs;
            } else {
                v = *(const float4*)&nf[(size_t)n * 64 + (s - 16) * 4];
            }
        }
        int k0 = s * 4;
        sX[(k0 + 0) * 128 + m] = v.x;
        sX[(k0 + 1) * 128 + m] = v.y;
        sX[(k0 + 2) * 128 + m] = v.z;
        sX[(k0 + 3) * 128 + m] = v.w;
    }
    __syncthreads();

    u64 uacc2[8][2];
    #pragma unroll
    for (int i = 0; i < 8; ++i) { uacc2[i][0] = 0ull; uacc2[i][1] = 0ull; }

    #pragma unroll 1
    for (int chunk = 0; chunk < 2; ++chunk) {
        const int c0 = chunk * 64;
        u64 acc2[8][2];
        #pragma unroll
        for (int i = 0; i < 8; ++i) { acc2[i][0] = 0ull; acc2[i][1] = 0ull; }

        #pragma unroll 1
        for (int kc = 0; kc < 4; ++kc) {
            __syncthreads();
            #pragma unroll
            for (int i = tid; i < 512; i += 256) {
                int row = i >> 4;
                int cq  = i & 15;
                *(float4*)&sW[row * 64 + cq * 4] =
                    *(const float4*)&Wn1[(size_t)(kc * 32 + row) * 128 + c0 + cq * 4];
            }
            __syncthreads();
            #pragma unroll
            for (int kk = 0; kk < 32; ++kk) {
                const float* xr = &sX[(kc * 32 + kk) * 128 + ty * 8];
                float4 a0 = *(const float4*)xr;
                float4 a1 = *(const float4*)(xr + 4);
                F4U2 B; B.f = *(const float4*)&sW[kk * 64 + tx * 4];
                u64 ad[8];
                DUP2(ad[0], a0.x); DUP2(ad[1], a0.y); DUP2(ad[2], a0.z); DUP2(ad[3], a0.w);
                DUP2(ad[4], a1.x); DUP2(ad[5], a1.y); DUP2(ad[6], a1.z); DUP2(ad[7], a1.w);
                #pragma unroll
                for (int i = 0; i < 8; ++i) {
                    FMA2(acc2[i][0], ad[i], B.u[0]);
                    FMA2(acc2[i][1], ad[i], B.u[1]);
                }
            }
        }

        float acc[8][4];
        #pragma unroll
        for (int i = 0; i < 8; ++i) {
            U2F p0, p1; p0.u = acc2[i][0]; p1.u = acc2[i][1];
            acc[i][0] = p0.f.x; acc[i][1] = p0.f.y;
            acc[i][2] = p1.f.x; acc[i][3] = p1.f.y;
        }
        float bj0 = bn1[c0 + tx * 4 + 0], bj1 = bn1[c0 + tx * 4 + 1];
        float bj2 = bn1[c0 + tx * 4 + 2], bj3 = bn1[c0 + tx * 4 + 3];
        #pragma unroll
        for (int i = 0; i < 8; ++i) {
            acc[i][0] = fmaxf(acc[i][0] + bj0, 0.0f);
            acc[i][1] = fmaxf(acc[i][1] + bj1, 0.0f);
            acc[i][2] = fmaxf(acc[i][2] + bj2, 0.0f);
            acc[i][3] = fmaxf(acc[i][3] + bj3, 0.0f);
        }

        #pragma unroll
        for (int i = 0; i < 8; ++i) {
            sH[(tx * 4 + 0) * 132 + ty * 8 + i] = acc[i][0];
            sH[(tx * 4 + 1) * 132 + ty * 8 + i] = acc[i][1];
            sH[(tx * 4 + 2) * 132 + ty * 8 + i] = acc[i][2];
            sH[(tx * 4 + 3) * 132 + ty * 8 + i] = acc[i][3];
        }
        __syncthreads();
        #pragma unroll
        for (int hh = 0; hh < 64; ++hh) {
            const float* hr = &sH[hh * 132 + ty * 8];
            float4 a0 = *(const float4*)hr;
            float4 a1 = *(const float4*)(hr + 4);
            F4U2 B; B.f = *(const float4*)&sWn2[(c0 + hh) * 64 + tx * 4];
            u64 ad[8];
            DUP2(ad[0], a0.x); DUP2(ad[1], a0.y); DUP2(ad[2], a0.z); DUP2(ad[3], a0.w);
            DUP2(ad[4], a1.x); DUP2(ad[5], a1.y); DUP2(ad[6], a1.z); DUP2(ad[7], a1.w);
            #pragma unroll
            for (int i = 0; i < 8; ++i) {
                FMA2(uacc2[i][0], ad[i], B.u[0]);
                FMA2(uacc2[i][1], ad[i], B.u[1]);
            }
        }
        __syncthreads();
    }

    float o0 = bn2[tx * 4 + 0], o1 = bn2[tx * 4 + 1];
    float o2 = bn2[tx * 4 + 2], o3 = bn2[tx * 4 + 3];
    #pragma unroll
    for (int i = 0; i < 8; ++i) {
        int n = n0 + ty * 8 + i;
        if (n < N) {
            float4 o = make_float4(lane_of(uacc2[i][0], 0) + o0,
                                   lane_of(uacc2[i][0], 1) + o1,
                                   lane_of(uacc2[i][1], 0) + o2,
                                   lane_of(uacc2[i][1], 1) + o3);
            *(float4*)&unf_out[(size_t)n * 64 + tx * 4] = o;
        }
    }
}

// ---------------------------------------------------------------------------
// launch
// ---------------------------------------------------------------------------
extern "C" void kernel_launch(void* const* d_in, const int* in_sizes, int n_in,
                              void* d_out, int out_size)
{
    const float* nf  = (const float*)d_in[0];
    const float* ef  = (const float*)d_in[1];
    const float* We1 = (const float*)d_in[2];
    const float* be1 = (const float*)d_in[3];
    const float* We2 = (const float*)d_in[4];
    const float* be2 = (const float*)d_in[5];
    const float* Wa1 = (const float*)d_in[6];
    const float* ba1 = (const float*)d_in[7];
    const float* Wa2 = (const float*)d_in[8];
    const float* ba2 = (const float*)d_in[9];
    const float* Wn1 = (const float*)d_in[10];
    const float* bn1 = (const float*)d_in[11];
    const float* Wn2 = (const float*)d_in[12];
    const float* bn2 = (const float*)d_in[13];
    const int*   src = (const int*)d_in[14];
    const int*   dst = (const int*)d_in[15];

    const int N = in_sizes[0] / 64;
    const int E = in_sizes[14];

    float* unf_out = (float*)d_out;                       // [N,64] first (ref return order)
    float* uef_out = (float*)d_out + (size_t)N * 64;      // [E,64] second

    cudaFuncSetAttribute(kp_nodes, cudaFuncAttributeMaxDynamicSharedMemorySize, KP_SMEM_BYTES);
    cudaFuncSetAttribute(k1_edge, cudaFuncAttributeMaxDynamicSharedMemorySize, K1_SMEM_BYTES);
    cudaFuncSetAttribute(k3_node, cudaFuncAttributeMaxDynamicSharedMemorySize, NODE_SMEM_BYTES);

    k0_init<<<(N * 64 + 255) / 256, 256>>>(N);
    k_prep<<<224, 256>>>(We1, Wa1, We2);
    kp_nodes<<<(N + 127) / 128, 512, KP_SMEM_BYTES>>>(nf, N);
    k1_edge<<<(E + 127) / 128, 512, K1_SMEM_BYTES>>>(
        ef, be1, be2, ba1, ba2, Wa2, src, dst, uef_out, E);
    k3_node<<<(N + 127) / 128, 256, NODE_SMEM_BYTES>>>(
        nf, Wn1, bn1, Wn2, bn2, unf_out, N);
}

// round 16
// speedup vs baseline: 1.8571x; 1.8571x over previous
#include <cuda_runtime.h>
#include <cuda_bf16.h>
#include <mma.h>
#include <stdint.h>
#include <math.h>

using namespace nvcuda;

typedef unsigned long long u64;
typedef unsigned int u32;

// ---------------------------------------------------------------------------
// Scratch (static __device__ arrays; no dynamic allocation allowed)
// ---------------------------------------------------------------------------
#define MAX_N 50048

__device__ __align__(16) float g_segsum[MAX_N];
__device__ __align__(16) float g_cnt[MAX_N];
__device__ __align__(16) float g_agg[50000 * 64];

// Per-node precomputed GEMM slabs (fp32):
//   g_P[n][0..127]   = nf[n] @ We1-part rows 64..127   (He src)
//   g_P[n][128..255] = nf[n] @ Wa1-part rows 64..127   (attn src)
//   g_P[n][256..383] = nf[n] @ We1-part rows 128..191  (He dst)
//   g_P[n][384..511] = nf[n] @ Wa1-part rows 128..191  (attn dst)
__device__ __align__(16) float g_P[(size_t)MAX_N * 512];

// Pre-split weights (filled by k_prep), row-major bf16 hi/lo images.
// W1cat: [192][256]  (cols 0..127 = We1, 128..255 = Wa1)
__device__ __align__(16) __nv_bfloat16 gW1h[192 * 256];
__device__ __align__(16) __nv_bfloat16 gW1l[192 * 256];
// We2: [128][64]
__device__ __align__(16) __nv_bfloat16 gW2h[128 * 64];
__device__ __align__(16) __nv_bfloat16 gW2l[128 * 64];

// fp32 -> bf16 hi/lo split
__device__ __forceinline__ void split2(float v, unsigned short& h, unsigned short& l) {
    __nv_bfloat16 bh = __float2bfloat16_rn(v);
    float r = v - __bfloat162float(bh);
    __nv_bfloat16 bl = __float2bfloat16_rn(r);
    h = __bfloat16_as_ushort(bh);
    l = __bfloat16_as_ushort(bl);
}

__device__ __forceinline__ void red_add_v4(float* p, float4 v) {
    asm volatile("red.global.add.v4.f32 [%0], {%1,%2,%3,%4};"
                 :: "l"(__cvta_generic_to_global(p)),
                    "f"(v.x), "f"(v.y), "f"(v.z), "f"(v.w)
                 : "memory");
}

// ---------------------------------------------------------------------------
// K0: zero-init scratch
// ---------------------------------------------------------------------------
__global__ void k0_init(int N) {
    int i = blockIdx.x * blockDim.x + threadIdx.x;
    if (i < N) {
        g_segsum[i] = 0.0f;
        g_cnt[i]    = 0.0f;
    }
    if (i < N * 64) g_agg[i] = 0.0f;
}

// ---------------------------------------------------------------------------
// K_PREP: bf16 hi/lo split of weights into row-major global images.
// ---------------------------------------------------------------------------
__global__ void k_prep(const float* __restrict__ We1, const float* __restrict__ Wa1,
                       const float* __restrict__ We2) {
    int idx = blockIdx.x * blockDim.x + threadIdx.x;
    if (idx < 49152) {                    // 192*256
        int n = idx & 255, k = idx >> 8;
        float v = (n < 128) ? We1[(size_t)k * 128 + n]
                            : Wa1[(size_t)k * 128 + (n - 128)];
        unsigned short h, l; split2(v, h, l);
        gW1h[idx] = __ushort_as_bfloat16(h);
        gW1l[idx] = __ushort_as_bfloat16(l);
    } else if (idx < 49152 + 8192) {      // 128*64
        int t = idx - 49152;
        float v = We2[t];
        unsigned short h, l; split2(v, h, l);
        gW2h[t] = __ushort_as_bfloat16(h);
        gW2l[t] = __ushort_as_bfloat16(l);
    }
}

// ---------------------------------------------------------------------------
// Shared WMMA types / layout constants
// ---------------------------------------------------------------------------
typedef wmma::fragment<wmma::accumulator, 16, 16, 16, float> FragC;
typedef wmma::fragment<wmma::matrix_a, 16, 16, 16, __nv_bfloat16, wmma::row_major> FragA;
typedef wmma::fragment<wmma::matrix_b, 16, 16, 16, __nv_bfloat16, wmma::row_major> FragB;

#define LDX  72
#define LDW1 264
#define LDC  136
#define LDH  136
#define LDW2 72

// k1 smem byte map (total 212480)
#define SM_XH   0
#define SM_XL   18432
#define SM_W1H  36864
#define SM_W1L  70656
#define SM_C    104448
#define SM_W2H  174080
#define SM_W2L  192512
#define SM_HH   0
#define SM_HL   34816
#define SM_SRC  210944
#define SM_DST  211456
#define SM_LOG  211968
#define K1_SMEM_BYTES 212480
// kp uses [0, 104448) of the same map
#define KP_SMEM_BYTES 104448

// gather 128 rows x 64 cols fp32 -> split -> sXh/sXl  (rows guarded)
__device__ __forceinline__ void gather_split_64(
    char* smc, const float* __restrict__ base, int row0, int rowMax, int tid)
{
    __nv_bfloat16* sXh = (__nv_bfloat16*)(smc + SM_XH);
    __nv_bfloat16* sXl = (__nv_bfloat16*)(smc + SM_XL);
    for (int it = 0; it < 4; ++it) {
        int task = it * 512 + tid;        // 0..2047 = 128 rows x 16 float4
        int m = task >> 4;
        int s = task & 15;
        float4 v = make_float4(0.f, 0.f, 0.f, 0.f);
        if (row0 + m < rowMax)
            v = *(const float4*)&base[(size_t)(row0 + m) * 64 + s * 4];
        unsigned short h0,l0,h1,l1,h2,l2,h3,l3;
        split2(v.x, h0, l0); split2(v.y, h1, l1);
        split2(v.z, h2, l2); split2(v.w, h3, l3);
        u32* ph = (u32*)(sXh + (size_t)m * LDX + s * 4);
        u32* pl = (u32*)(sXl + (size_t)m * LDX + s * 4);
        ph[0] = (u32)h0 | ((u32)h1 << 16);
        ph[1] = (u32)h2 | ((u32)h3 << 16);
        pl[0] = (u32)l0 | ((u32)l1 << 16);
        pl[1] = (u32)l2 | ((u32)l3 << 16);
    }
}

// stage 64 rows (rowbase..) x 256 cols of W1cat h+l into sW1
__device__ __forceinline__ void stage_w1_slab(char* smc, int rowbase, int tid) {
    const u32* sh = (const u32*)gW1h;
    const u32* sl = (const u32*)gW1l;
    u32* dh = (u32*)(smc + SM_W1H);
    u32* dl = (u32*)(smc + SM_W1L);
    for (int i = tid; i < 16384; i += 512) {     // 2 imgs x 64 rows x 128 u32
        int img = i >> 13;
        int rem = i & 8191;
        int row = rem >> 7, c2 = rem & 127;
        u32 v = (img ? sl : sh)[(size_t)(rowbase + row) * 128 + c2];
        (img ? dl : dh)[row * (LDW1 / 2) + c2] = v;
    }
}

// ---------------------------------------------------------------------------
// KP: per-node P table.  CTA = 128 nodes, 512 threads, 2 phases (src/dst role).
// ---------------------------------------------------------------------------
__global__ __launch_bounds__(512, 1)
void kp_nodes(const float* __restrict__ nf, int N)
{
    extern __shared__ char smc[];
    const int tid = threadIdx.x;
    const int w   = tid >> 5;
    const int wr  = w >> 1;
    const int wc  = w & 1;
    const int n0  = blockIdx.x * 128;

    gather_split_64(smc, nf, n0, N, tid);

    __nv_bfloat16* sXh  = (__nv_bfloat16*)(smc + SM_XH);
    __nv_bfloat16* sXl  = (__nv_bfloat16*)(smc + SM_XL);
    __nv_bfloat16* sW1h = (__nv_bfloat16*)(smc + SM_W1H);
    __nv_bfloat16* sW1l = (__nv_bfloat16*)(smc + SM_W1L);

    #pragma unroll 1
    for (int ph = 0; ph < 2; ++ph) {
        __syncthreads();
        stage_w1_slab(smc, 64 + ph * 64, tid);
        __syncthreads();

        FragC cc[8];
        #pragma unroll
        for (int j = 0; j < 8; ++j) wmma::fill_fragment(cc[j], 0.0f);
        #pragma unroll 1
        for (int k = 0; k < 4; ++k) {
            FragA ah, al;
            wmma::load_matrix_sync(ah, sXh + (size_t)wr * 16 * LDX + k * 16, LDX);
            wmma::load_matrix_sync(al, sXl + (size_t)wr * 16 * LDX + k * 16, LDX);
            #pragma unroll
            for (int j = 0; j < 8; ++j) {
                int col = wc * 128 + j * 16;
                FragB bh, bl;
                wmma::load_matrix_sync(bh, sW1h + (size_t)k * 16 * LDW1 + col, LDW1);
                wmma::load_matrix_sync(bl, sW1l + (size_t)k * 16 * LDW1 + col, LDW1);
                wmma::mma_sync(cc[j], ah, bh, cc[j]);
                wmma::mma_sync(cc[j], ah, bl, cc[j]);
                wmma::mma_sync(cc[j], al, bh, cc[j]);
            }
        }
        // store straight to global (g_P padded to MAX_N rows; always in-bounds)
        float* prow = g_P + (size_t)(n0 + wr * 16) * 512 + ph * 256 + wc * 128;
        #pragma unroll
        for (int j = 0; j < 8; ++j)
            wmma::store_matrix_sync(prow + j * 16, cc[j], 512, wmma::mem_row_major);
    }
}

// ---------------------------------------------------------------------------
// K1: edge kernel.  GEMM1 over ef slab only (K=64); P_src/P_dst added as
//     exact fp32 in COALESCED, MLP-BATCHED passes (8 independent float4
//     loads in flight; warp = one row x 128 cols per batch-step).
// ---------------------------------------------------------------------------
__global__ __launch_bounds__(512, 1)
void k1_edge(const float* __restrict__ ef,
             const float* __restrict__ be1, const float* __restrict__ be2,
             const float* __restrict__ ba1, const float* __restrict__ ba2,
             const float* __restrict__ Wa2,
             const int* __restrict__ src,   const int* __restrict__ dst,
             float* __restrict__ uef_out, int E)
{
    extern __shared__ char smc[];
    const int tid = threadIdx.x;
    const int w   = tid >> 5;
    const int wr  = w >> 1;          // row tile 0..7
    const int wc  = w & 1;           // col half 0..1
    const int e0  = blockIdx.x * 128;

    float* sLog = (float*)(smc + SM_LOG);
    int*   sSrc = (int*)(smc + SM_SRC);
    int*   sDst = (int*)(smc + SM_DST);
    if (tid < 128) {
        sLog[tid] = 0.0f;
        int e = e0 + tid;
        sSrc[tid] = (e < E) ? src[e] : 0;
        sDst[tid] = (e < E) ? dst[e] : 0;
    }

    gather_split_64(smc, ef, e0, E, tid);     // contiguous, fully coalesced
    stage_w1_slab(smc, 0, tid);               // W1cat rows 0..63, all 256 cols
    {   // stage We2 (h+l) up front — its smem region is free until GEMM2
        const u32* sh = (const u32*)gW2h;
        const u32* sl = (const u32*)gW2l;
        u32* dh = (u32*)(smc + SM_W2H);
        u32* dl = (u32*)(smc + SM_W2L);
        for (int i = tid; i < 8192; i += 512) {   // 2 imgs x 128 rows x 32 u32
            int img = i >> 12;
            int rem = i & 4095;
            int r2 = rem >> 5, c2 = rem & 31;
            u32 v = (img ? sl : sh)[r2 * 32 + c2];
            (img ? dl : dh)[r2 * (LDW2 / 2) + c2] = v;
        }
    }
    __syncthreads();                          // --- sync A ---

    __nv_bfloat16* sXh  = (__nv_bfloat16*)(smc + SM_XH);
    __nv_bfloat16* sXl  = (__nv_bfloat16*)(smc + SM_XL);
    __nv_bfloat16* sW1h = (__nv_bfloat16*)(smc + SM_W1H);
    __nv_bfloat16* sW1l = (__nv_bfloat16*)(smc + SM_W1L);
    float* sC = (float*)(smc + SM_C);

    // --- GEMM1a (He cols wc*64..): only 4 C frags live ---
    {
        FragC cHe[4];
        #pragma unroll
        for (int j = 0; j < 4; ++j) wmma::fill_fragment(cHe[j], 0.0f);
        #pragma unroll 1
        for (int k = 0; k < 4; ++k) {
            FragA ah, al;
            wmma::load_matrix_sync(ah, sXh + (size_t)wr * 16 * LDX + k * 16, LDX);
            wmma::load_matrix_sync(al, sXl + (size_t)wr * 16 * LDX + k * 16, LDX);
            #pragma unroll
            for (int j = 0; j < 4; ++j) {
                int ce = wc * 64 + j * 16;
                FragB bh, bl;
                wmma::load_matrix_sync(bh, sW1h + (size_t)k * 16 * LDW1 + ce, LDW1);
                wmma::load_matrix_sync(bl, sW1l + (size_t)k * 16 * LDW1 + ce, LDW1);
                wmma::mma_sync(cHe[j], ah, bh, cHe[j]);
                wmma::mma_sync(cHe[j], ah, bl, cHe[j]);
                wmma::mma_sync(cHe[j], al, bh, cHe[j]);
            }
        }
        #pragma unroll
        for (int j = 0; j < 4; ++j)
            wmma::store_matrix_sync(sC + (size_t)wr * 16 * LDC + wc * 64 + j * 16,
                                    cHe[j], LDC, wmma::mem_row_major);
    }

    // --- GEMM1b (Ha cols 128+wc*64..): frags held briefly ---
    FragC cHa[4];
    #pragma unroll
    for (int j = 0; j < 4; ++j) wmma::fill_fragment(cHa[j], 0.0f);
    #pragma unroll 1
    for (int k = 0; k < 4; ++k) {
        FragA ah, al;
        wmma::load_matrix_sync(ah, sXh + (size_t)wr * 16 * LDX + k * 16, LDX);
        wmma::load_matrix_sync(al, sXl + (size_t)wr * 16 * LDX + k * 16, LDX);
        #pragma unroll
        for (int j = 0; j < 4; ++j) {
            int ca = 128 + wc * 64 + j * 16;
            FragB bh, bl;
            wmma::load_matrix_sync(bh, sW1h + (size_t)k * 16 * LDW1 + ca, LDW1);
            wmma::load_matrix_sync(bl, sW1l + (size_t)k * 16 * LDW1 + ca, LDW1);
            wmma::mma_sync(cHa[j], ah, bh, cHa[j]);
            wmma::mma_sync(cHa[j], ah, bl, cHa[j]);
            wmma::mma_sync(cHa[j], al, bh, cHa[j]);
        }
    }
    __syncthreads();                          // --- sync B: He in sC; X dead ---

    // --- He pass: sC + P -> bias/ReLU/split -> sH  (batched MLP=8) ---
    __nv_bfloat16* sHh = (__nv_bfloat16*)(smc + SM_HH);
    __nv_bfloat16* sHl = (__nv_bfloat16*)(smc + SM_HL);
    #pragma unroll 1
    for (int half = 0; half < 2; ++half) {
        float4 vs[4], vd[4];
        #pragma unroll
        for (int t = 0; t < 4; ++t) {
            int task = (half * 4 + t) * 512 + tid;
            int row = task >> 5, c4 = task & 31;
            vs[t] = *(const float4*)(g_P + (size_t)sSrc[row] * 512 + c4 * 4);
            vd[t] = *(const float4*)(g_P + (size_t)sDst[row] * 512 + 256 + c4 * 4);
        }
        #pragma unroll
        for (int t = 0; t < 4; ++t) {
            int task = (half * 4 + t) * 512 + tid;
            int row = task >> 5, c4 = task & 31;
            int col = c4 * 4;
            float4 c = *(const float4*)(sC + (size_t)row * LDC + col);
            float f0 = fmaxf(c.x + vs[t].x + vd[t].x + be1[col + 0], 0.0f);
            float f1 = fmaxf(c.y + vs[t].y + vd[t].y + be1[col + 1], 0.0f);
            float f2 = fmaxf(c.z + vs[t].z + vd[t].z + be1[col + 2], 0.0f);
            float f3 = fmaxf(c.w + vs[t].w + vd[t].w + be1[col + 3], 0.0f);
            unsigned short h0,l0,h1,l1,h2,l2,h3,l3;
            split2(f0, h0, l0); split2(f1, h1, l1);
            split2(f2, h2, l2); split2(f3, h3, l3);
            u32* ph = (u32*)(sHh + (size_t)row * LDH + col);
            u32* pl = (u32*)(sHl + (size_t)row * LDH + col);
            ph[0] = (u32)h0 | ((u32)h1 << 16);
            ph[1] = (u32)h2 | ((u32)h3 << 16);
            pl[0] = (u32)l0 | ((u32)l1 << 16);
            pl[1] = (u32)l2 | ((u32)l3 << 16);
        }
    }
    __syncthreads();                          // --- sync C: sC free ---

    // --- dump Ha -> sC ---
    #pragma unroll
    for (int j = 0; j < 4; ++j)
        wmma::store_matrix_sync(sC + (size_t)wr * 16 * LDC + wc * 64 + j * 16,
                                cHa[j], LDC, wmma::mem_row_major);
    __syncthreads();                          // --- sync D ---

    // --- attn pass (batched MLP=8; warp = one row; single writer per row) ---
    {
        int lane = tid & 31;
        #pragma unroll 1
        for (int half = 0; half < 2; ++half) {
            float4 vs[4], vd[4];
            #pragma unroll
            for (int t = 0; t < 4; ++t) {
                int task = (half * 4 + t) * 512 + tid;
                int row = task >> 5, c4 = task & 31;
                vs[t] = *(const float4*)(g_P + (size_t)sSrc[row] * 512 + 128 + c4 * 4);
                vd[t] = *(const float4*)(g_P + (size_t)sDst[row] * 512 + 384 + c4 * 4);
            }
            #pragma unroll
            for (int t = 0; t < 4; ++t) {
                int task = (half * 4 + t) * 512 + tid;
                int row = task >> 5, c4 = task & 31;
                int col = c4 * 4;
                float4 c = *(const float4*)(sC + (size_t)row * LDC + col);
                float p =
                    fmaxf(c.x + vs[t].x + vd[t].x + ba1[col + 0], 0.0f) * Wa2[col + 0]
                  + fmaxf(c.y + vs[t].y + vd[t].y + ba1[col + 1], 0.0f) * Wa2[col + 1]
                  + fmaxf(c.z + vs[t].z + vd[t].z + ba1[col + 2], 0.0f) * Wa2[col + 2]
                  + fmaxf(c.w + vs[t].w + vd[t].w + ba1[col + 3], 0.0f) * Wa2[col + 3];
                p += __shfl_xor_sync(0xFFFFFFFFu, p, 16);
                p += __shfl_xor_sync(0xFFFFFFFFu, p, 8);
                p += __shfl_xor_sync(0xFFFFFFFFu, p, 4);
                p += __shfl_xor_sync(0xFFFFFFFFu, p, 2);
                p += __shfl_xor_sync(0xFFFFFFFFu, p, 1);
                // row = (half*4+t)*16 + w : exactly one (warp, step) owns each row
                if (lane == 0) sLog[row] = p;
            }
        }
    }
    __syncthreads();                          // --- sync E ---

    // --- GEMM2: uef = H @ We2 (K=128; each warp 2 j-tiles of 32 cols) ---
    {
        FragC cU[2];
        wmma::fill_fragment(cU[0], 0.0f);
        wmma::fill_fragment(cU[1], 0.0f);
        __nv_bfloat16* sW2h = (__nv_bfloat16*)(smc + SM_W2H);
        __nv_bfloat16* sW2l = (__nv_bfloat16*)(smc + SM_W2L);
        #pragma unroll 1
        for (int k = 0; k < 8; ++k) {
            FragA ah, al;
            wmma::load_matrix_sync(ah, sHh + (size_t)wr * 16 * LDH + k * 16, LDH);
            wmma::load_matrix_sync(al, sHl + (size_t)wr * 16 * LDH + k * 16, LDH);
            #pragma unroll
            for (int j = 0; j < 2; ++j) {
                int col = wc * 32 + j * 16;
                FragB bh, bl;
                wmma::load_matrix_sync(bh, sW2h + (size_t)k * 16 * LDW2 + col, LDW2);
                wmma::load_matrix_sync(bl, sW2l + (size_t)k * 16 * LDW2 + col, LDW2);
                wmma::mma_sync(cU[j], ah, bh, cU[j]);
                wmma::mma_sync(cU[j], ah, bl, cU[j]);
                wmma::mma_sync(cU[j], al, bh, cU[j]);
            }
        }
        #pragma unroll
        for (int j = 0; j < 2; ++j)
            wmma::store_matrix_sync(sC + (size_t)wr * 16 * LDC + wc * 32 + j * 16,
                                    cU[j], LDC, wmma::mem_row_major);
    }
    __syncthreads();                          // --- sync F ---

    // --- epilogue: logits->exp, segment atomics, uef write, aggregate ---
    if (tid < 128) {
        int e = e0 + tid;
        if (e < E) {
            float lg = sLog[tid] + ba2[0];
            float ex = __expf(lg);        // no max-subtraction: logits are O(1)
            int d = sDst[tid];
            atomicAdd(&g_segsum[d], ex);
            atomicAdd(&g_cnt[d], 1.0f);
            float* orow = uef_out + (size_t)e * 64;
            float* arow = g_agg + (size_t)d * 64;
            const float* crow = sC + (size_t)tid * LDC;
            #pragma unroll
            for (int q = 0; q < 16; ++q) {
                float4 c = *(const float4*)(crow + q * 4);
                float4 o = make_float4(c.x + be2[q*4 + 0], c.y + be2[q*4 + 1],
                                       c.z + be2[q*4 + 2], c.w + be2[q*4 + 3]);
                *(float4*)(orow + q * 4) = o;
                float4 vv = make_float4(o.x * ex, o.y * ex, o.z * ex, o.w * ex);
                red_add_v4(arow + q * 4, vv);
            }
        }
    }
}

// ---------------------------------------------------------------------------
// K3: node MLP (proven version: 256 threads, FFMA2+DUP2)
// ---------------------------------------------------------------------------
#define FMA2(d, a, b) asm("fma.rn.f32x2 %0, %1, %2, %0;" : "+l"(d) : "l"(a), "l"(b))
#define DUP2(d, s)    asm("mov.b64 %0, {%1, %1};" : "=l"(d) : "f"(s))
union F4U2 { float4 f; u64 u[2]; };
union U2F  { u64 u; float2 f; };
__device__ __forceinline__ float lane_of(u64 v, int h) {
    U2F t; t.u = v; return h ? t.f.y : t.f.x;
}

#define NODE_SMEM_FLOATS (16384 + 2048 + 8448 + 8192 + 128)
#define NODE_SMEM_BYTES  (NODE_SMEM_FLOATS * 4)

__global__ __launch_bounds__(256, 1)
void k3_node(const float* __restrict__ nf,
             const float* __restrict__ Wn1, const float* __restrict__ bn1,
             const float* __restrict__ Wn2, const float* __restrict__ bn2,
             float* __restrict__ unf_out, int N)
{
    extern __shared__ float sm[];
    float* sX   = sm;            // [128][128]
    float* sW   = sX + 16384;    // [32][64]
    float* sH   = sW + 2048;     // [64][132]
    float* sWn2 = sH + 8448;     // [128][64]
    float* sRs  = sWn2 + 8192;   // [128]

    const int tid = threadIdx.x;
    const int tx  = tid & 15;
    const int ty  = tid >> 4;
    const int n0  = blockIdx.x * 128;

    #pragma unroll
    for (int i = tid; i < 2048; i += 256)
        ((float4*)sWn2)[i] = ((const float4*)Wn2)[i];
    if (tid < 128) {
        int n = n0 + tid;
        float rs = 0.0f;
        if (n < N) {
            float c = g_cnt[n];
            if (c > 0.5f) rs = 1.0f / (g_segsum[n] * c);
        }
        sRs[tid] = rs;
    }
    __syncthreads();

    for (int it = 0; it < 16; ++it) {
        int task = it * 256 + tid;
        if (task >= 4096) break;
        int m = task & 127;
        int s = task >> 7;
        int n = n0 + m;
        float4 v = make_float4(0.f, 0.f, 0.f, 0.f);
        if (n < N) {
            if (s < 16) {
                v = *(const float4*)&g_agg[(size_t)n * 64 + s * 4];
                float rs = sRs[m];
                v.x *= rs; v.y *= rs; v.z *= rs; v.w *= rs;
            } else {
                v = *(const float4*)&nf[(size_t)n * 64 + (s - 16) * 4];
            }
        }
        int k0 = s * 4;
        sX[(k0 + 0) * 128 + m] = v.x;
        sX[(k0 + 1) * 128 + m] = v.y;
        sX[(k0 + 2) * 128 + m] = v.z;
        sX[(k0 + 3) * 128 + m] = v.w;
    }
    __syncthreads();

    u64 uacc2[8][2];
    #pragma unroll
    for (int i = 0; i < 8; ++i) { uacc2[i][0] = 0ull; uacc2[i][1] = 0ull; }

    #pragma unroll 1
    for (int chunk = 0; chunk < 2; ++chunk) {
        const int c0 = chunk * 64;
        u64 acc2[8][2];
        #pragma unroll
        for (int i = 0; i < 8; ++i) { acc2[i][0] = 0ull; acc2[i][1] = 0ull; }

        #pragma unroll 1
        for (int kc = 0; kc < 4; ++kc) {
            __syncthreads();
            #pragma unroll
            for (int i = tid; i < 512; i += 256) {
                int row = i >> 4;
                int cq  = i & 15;
                *(float4*)&sW[row * 64 + cq * 4] =
                    *(const float4*)&Wn1[(size_t)(kc * 32 + row) * 128 + c0 + cq * 4];
            }
            __syncthreads();
            #pragma unroll
            for (int kk = 0; kk < 32; ++kk) {
                const float* xr = &sX[(kc * 32 + kk) * 128 + ty * 8];
                float4 a0 = *(const float4*)xr;
                float4 a1 = *(const float4*)(xr + 4);
                F4U2 B; B.f = *(const float4*)&sW[kk * 64 + tx * 4];
                u64 ad[8];
                DUP2(ad[0], a0.x); DUP2(ad[1], a0.y); DUP2(ad[2], a0.z); DUP2(ad[3], a0.w);
                DUP2(ad[4], a1.x); DUP2(ad[5], a1.y); DUP2(ad[6], a1.z); DUP2(ad[7], a1.w);
                #pragma unroll
                for (int i = 0; i < 8; ++i) {
                    FMA2(acc2[i][0], ad[i], B.u[0]);
                    FMA2(acc2[i][1], ad[i], B.u[1]);
                }
            }
        }

        float acc[8][4];
        #pragma unroll
        for (int i = 0; i < 8; ++i) {
            U2F p0, p1; p0.u = acc2[i][0]; p1.u = acc2[i][1];
            acc[i][0] = p0.f.x; acc[i][1] = p0.f.y;
            acc[i][2] = p1.f.x; acc[i][3] = p1.f.y;
        }
        float bj0 = bn1[c0 + tx * 4 + 0], bj1 = bn1[c0 + tx * 4 + 1];
        float bj2 = bn1[c0 + tx * 4 + 2], bj3 = bn1[c0 + tx * 4 + 3];
        #pragma unroll
        for (int i = 0; i < 8; ++i) {
            acc[i][0] = fmaxf(acc[i][0] + bj0, 0.0f);
            acc[i][1] = fmaxf(acc[i][1] + bj1, 0.0f);
            acc[i][2] = fmaxf(acc[i][2] + bj2, 0.0f);
            acc[i][3] = fmaxf(acc[i][3] + bj3, 0.0f);
        }

        #pragma unroll
        for (int i = 0; i < 8; ++i) {
            sH[(tx * 4 + 0) * 132 + ty * 8 + i] = acc[i][0];
            sH[(tx * 4 + 1) * 132 + ty * 8 + i] = acc[i][1];
            sH[(tx * 4 + 2) * 132 + ty * 8 + i] = acc[i][2];
            sH[(tx * 4 + 3) * 132 + ty * 8 + i] = acc[i][3];
        }
        __syncthreads();
        #pragma unroll
        for (int hh = 0; hh < 64; ++hh) {
            const float* hr = &sH[hh * 132 + ty * 8];
            float4 a0 = *(const float4*)hr;
            float4 a1 = *(const float4*)(hr + 4);
            F4U2 B; B.f = *(const float4*)&sWn2[(c0 + hh) * 64 + tx * 4];
            u64 ad[8];
            DUP2(ad[0], a0.x); DUP2(ad[1], a0.y); DUP2(ad[2], a0.z); DUP2(ad[3], a0.w);
            DUP2(ad[4], a1.x); DUP2(ad[5], a1.y); DUP2(ad[6], a1.z); DUP2(ad[7], a1.w);
            #pragma unroll
            for (int i = 0; i < 8; ++i) {
                FMA2(uacc2[i][0], ad[i], B.u[0]);
                FMA2(uacc2[i][1], ad[i], B.u[1]);
            }
        }
        __syncthreads();
    }

    float o0 = bn2[tx * 4 + 0], o1 = bn2[tx * 4 + 1];
    float o2 = bn2[tx * 4 + 2], o3 = bn2[tx * 4 + 3];
    #pragma unroll
    for (int i = 0; i < 8; ++i) {
        int n = n0 + ty * 8 + i;
        if (n < N) {
            float4 o = make_float4(lane_of(uacc2[i][0], 0) + o0,
                                   lane_of(uacc2[i][0], 1) + o1,
                                   lane_of(uacc2[i][1], 0) + o2,
                                   lane_of(uacc2[i][1], 1) + o3);
            *(float4*)&unf_out[(size_t)n * 64 + tx * 4] = o;
        }
    }
}

// ---------------------------------------------------------------------------
// launch
// ---------------------------------------------------------------------------
extern "C" void kernel_launch(void* const* d_in, const int* in_sizes, int n_in,
                              void* d_out, int out_size)
{
    const float* nf  = (const float*)d_in[0];
    const float* ef  = (const float*)d_in[1];
    const float* We1 = (const float*)d_in[2];
    const float* be1 = (const float*)d_in[3];
    const float* We2 = (const float*)d_in[4];
    const float* be2 = (const float*)d_in[5];
    const float* Wa1 = (const float*)d_in[6];
    const float* ba1 = (const float*)d_in[7];
    const float* Wa2 = (const float*)d_in[8];
    const float* ba2 = (const float*)d_in[9];
    const float* Wn1 = (const float*)d_in[10];
    const float* bn1 = (const float*)d_in[11];
    const float* Wn2 = (const float*)d_in[12];
    const float* bn2 = (const float*)d_in[13];
    const int*   src = (const int*)d_in[14];
    const int*   dst = (const int*)d_in[15];

    const int N = in_sizes[0] / 64;
    const int E = in_sizes[14];

    float* unf_out = (float*)d_out;                       // [N,64] first (ref return order)
    float* uef_out = (float*)d_out + (size_t)N * 64;      // [E,64] second

    cudaFuncSetAttribute(kp_nodes, cudaFuncAttributeMaxDynamicSharedMemorySize, KP_SMEM_BYTES);
    cudaFuncSetAttribute(k1_edge, cudaFuncAttributeMaxDynamicSharedMemorySize, K1_SMEM_BYTES);
    cudaFuncSetAttribute(k3_node, cudaFuncAttributeMaxDynamicSharedMemorySize, NODE_SMEM_BYTES);

    k0_init<<<(N * 64 + 255) / 256, 256>>>(N);
    k_prep<<<224, 256>>>(We1, Wa1, We2);
    kp_nodes<<<(N + 127) / 128, 512, KP_SMEM_BYTES>>>(nf, N);
    k1_edge<<<(E + 127) / 128, 512, K1_SMEM_BYTES>>>(
        ef, be1, be2, ba1, ba2, Wa2, src, dst, uef_out, E);
    k3_node<<<(N + 127) / 128, 256, NODE_SMEM_BYTES>>>(
        nf, Wn1, bn1, Wn2, bn2, unf_out, N);
}